// round 3
// baseline (speedup 1.0000x reference)
#include <cuda_runtime.h>

// CNF_plain: z[B,8], t scalar; MLP 9->128->128->8 with tanh; outputs
// dz_dt [B,8] and dlogp = -trace(J) [B,1], packed as [B*8 dz | B dlogp].
//
// trace = s1^T E s2 with E = W2 .* (W1[:D,:]^T W3^T), s1=1-h1^2, s2=1-h2^2.
// E precomputed per launch by prep_E.
//
// R3: back to 16 warps/SM for latency hiding; smem stores h only (s=1-h^2
// recomputed in-loop), 4-i inner blocks with float4 h broadcast.

#define Hh 128
#define Dd 8
#define NW 16          // warps per block
#define NS 8           // samples per warp per group
#define THREADS (NW * 32)
#define NBLK 152

// E in lane-permuted layout: p(i,j) = i*128 + (j&31)*4 + (j>>5)
__device__ float g_Ep[Hh * Hh];

__global__ void prep_E(const float* __restrict__ W1,
                       const float* __restrict__ W2,
                       const float* __restrict__ W3) {
    int idx = blockIdx.x * blockDim.x + threadIdx.x;   // 0..16383
    if (idx >= Hh * Hh) return;
    int i = idx >> 7, j = idx & 127;
    float c = 0.f;
#pragma unroll
    for (int d = 0; d < Dd; d++)
        c = fmaf(W1[d * Hh + i], W3[j * Dd + d], c);
    g_Ep[(i << 7) + ((j & 31) << 2) + (j >> 5)] = W2[i * Hh + j] * c;
}

// smem layout (floats):
//  hs        : NW*NS*128 = 16384 floats (h only)
//  W2s       : 16384 (permuted)
//  Es        : 16384 (permuted, from g_Ep)
//  W1s       : 9*128 (permuted)
//  W3s       : 128*8
//  b1s,b2s   : 128 each
//  b3s       : 8
#define SMEM_FLOATS (16384 * 3 + 9 * 128 + 128 * 8 + 128 + 128 + 8)
#define SMEM_BYTES (SMEM_FLOATS * 4)

__global__ __launch_bounds__(THREADS, 1)
void cnf_main(const float* __restrict__ z, const float* __restrict__ tptr,
              const float* __restrict__ W1, const float* __restrict__ b1,
              const float* __restrict__ W2, const float* __restrict__ b2,
              const float* __restrict__ W3, const float* __restrict__ b3,
              float* __restrict__ out, int B) {
    extern __shared__ float smem[];
    float* hs  = smem;                         // [NW][NS][128]
    float* W2s = smem + NW * NS * Hh;
    float* Es  = W2s + 16384;
    float* W1s = Es + 16384;
    float* W3s = W1s + 9 * Hh;
    float* b1s = W3s + Hh * Dd;
    float* b2s = b1s + Hh;
    float* b3s = b2s + Hh;

    // ---- stage weights into SMEM ----
    for (int idx = threadIdx.x; idx < Hh * Hh; idx += THREADS) {
        int i = idx >> 7, j = idx & 127;
        int p = (i << 7) + ((j & 31) << 2) + (j >> 5);
        W2s[p]  = W2[idx];
        Es[idx] = g_Ep[idx];                   // already permuted
    }
    for (int idx = threadIdx.x; idx < 9 * Hh; idx += THREADS) {
        int i = idx >> 7, j = idx & 127;
        W1s[(i << 7) + ((j & 31) << 2) + (j >> 5)] = W1[idx];
    }
    for (int idx = threadIdx.x; idx < Hh * Dd; idx += THREADS)
        W3s[idx] = W3[idx];
    if (threadIdx.x < Hh) {
        b1s[threadIdx.x] = b1[threadIdx.x];
        b2s[threadIdx.x] = b2[threadIdx.x];
    }
    if (threadIdx.x < Dd) b3s[threadIdx.x] = b3[threadIdx.x];
    __syncthreads();

    const int wid = threadIdx.x >> 5;
    const int lane = threadIdx.x & 31;
    float* myhs = hs + (wid * NS) * Hh;        // [NS][128]
    const float t = tptr[0];

    const int nGroups = B / NS;
    const int warpGlobal = blockIdx.x * NW + wid;
    const int totalWarps = gridDim.x * NW;

    for (int g = warpGlobal; g < nGroups; g += totalWarps) {
        const int s0 = g * NS;

        // ---- phase A: layer 1 (9 -> 128) ----
        float zreg[NS];
#pragma unroll
        for (int s = 0; s < NS; s++)
            zreg[s] = (lane < Dd) ? z[(size_t)(s0 + s) * Dd + lane] : t;

        float a[NS][4];
#pragma unroll
        for (int s = 0; s < NS; s++)
#pragma unroll
            for (int k = 0; k < 4; k++)
                a[s][k] = b1s[lane + 32 * k];

#pragma unroll
        for (int i = 0; i < 9; i++) {
            float4 w = *(const float4*)&W1s[(i << 7) + (lane << 2)];
#pragma unroll
            for (int s = 0; s < NS; s++) {
                float xi = __shfl_sync(0xffffffffu, zreg[s], i);
                a[s][0] = fmaf(xi, w.x, a[s][0]);
                a[s][1] = fmaf(xi, w.y, a[s][1]);
                a[s][2] = fmaf(xi, w.z, a[s][2]);
                a[s][3] = fmaf(xi, w.w, a[s][3]);
            }
        }

        __syncwarp();
#pragma unroll
        for (int s = 0; s < NS; s++)
#pragma unroll
            for (int k = 0; k < 4; k++)
                myhs[s * Hh + lane + 32 * k] = tanhf(a[s][k]);
        __syncwarp();

        // ---- phase B: fused GEMVs  b = h1@W2+b2,  r = s1@E ----
        float bacc[NS][4], racc[NS][4];
#pragma unroll
        for (int s = 0; s < NS; s++)
#pragma unroll
            for (int k = 0; k < 4; k++) {
                bacc[s][k] = b2s[lane + 32 * k];
                racc[s][k] = 0.f;
            }

        // 4 i's per iteration: weights held in regs, h broadcast as float4,
        // s-values recomputed as 1-h^2.
#pragma unroll 2
        for (int iq = 0; iq < Hh / 4; iq++) {
            const int i0 = iq * 4;
            float4 w0 = *(const float4*)&W2s[((i0 + 0) << 7) + (lane << 2)];
            float4 w1 = *(const float4*)&W2s[((i0 + 1) << 7) + (lane << 2)];
            float4 w2 = *(const float4*)&W2s[((i0 + 2) << 7) + (lane << 2)];
            float4 w3 = *(const float4*)&W2s[((i0 + 3) << 7) + (lane << 2)];
            float4 e0 = *(const float4*)&Es[((i0 + 0) << 7) + (lane << 2)];
            float4 e1 = *(const float4*)&Es[((i0 + 1) << 7) + (lane << 2)];
            float4 e2 = *(const float4*)&Es[((i0 + 2) << 7) + (lane << 2)];
            float4 e3 = *(const float4*)&Es[((i0 + 3) << 7) + (lane << 2)];
#pragma unroll
            for (int s = 0; s < NS; s++) {
                float4 hv = *(const float4*)&myhs[s * Hh + i0];
                float sx = fmaf(-hv.x, hv.x, 1.0f);
                float sy = fmaf(-hv.y, hv.y, 1.0f);
                float sz = fmaf(-hv.z, hv.z, 1.0f);
                float sw = fmaf(-hv.w, hv.w, 1.0f);
                bacc[s][0] = fmaf(hv.x, w0.x, bacc[s][0]);
                bacc[s][1] = fmaf(hv.x, w0.y, bacc[s][1]);
                bacc[s][2] = fmaf(hv.x, w0.z, bacc[s][2]);
                bacc[s][3] = fmaf(hv.x, w0.w, bacc[s][3]);
                racc[s][0] = fmaf(sx, e0.x, racc[s][0]);
                racc[s][1] = fmaf(sx, e0.y, racc[s][1]);
                racc[s][2] = fmaf(sx, e0.z, racc[s][2]);
                racc[s][3] = fmaf(sx, e0.w, racc[s][3]);
                bacc[s][0] = fmaf(hv.y, w1.x, bacc[s][0]);
                bacc[s][1] = fmaf(hv.y, w1.y, bacc[s][1]);
                bacc[s][2] = fmaf(hv.y, w1.z, bacc[s][2]);
                bacc[s][3] = fmaf(hv.y, w1.w, bacc[s][3]);
                racc[s][0] = fmaf(sy, e1.x, racc[s][0]);
                racc[s][1] = fmaf(sy, e1.y, racc[s][1]);
                racc[s][2] = fmaf(sy, e1.z, racc[s][2]);
                racc[s][3] = fmaf(sy, e1.w, racc[s][3]);
                bacc[s][0] = fmaf(hv.z, w2.x, bacc[s][0]);
                bacc[s][1] = fmaf(hv.z, w2.y, bacc[s][1]);
                bacc[s][2] = fmaf(hv.z, w2.z, bacc[s][2]);
                bacc[s][3] = fmaf(hv.z, w2.w, bacc[s][3]);
                racc[s][0] = fmaf(sz, e2.x, racc[s][0]);
                racc[s][1] = fmaf(sz, e2.y, racc[s][1]);
                racc[s][2] = fmaf(sz, e2.z, racc[s][2]);
                racc[s][3] = fmaf(sz, e2.w, racc[s][3]);
                bacc[s][0] = fmaf(hv.w, w3.x, bacc[s][0]);
                bacc[s][1] = fmaf(hv.w, w3.y, bacc[s][1]);
                bacc[s][2] = fmaf(hv.w, w3.z, bacc[s][2]);
                bacc[s][3] = fmaf(hv.w, w3.w, bacc[s][3]);
                racc[s][0] = fmaf(sw, e3.x, racc[s][0]);
                racc[s][1] = fmaf(sw, e3.y, racc[s][1]);
                racc[s][2] = fmaf(sw, e3.z, racc[s][2]);
                racc[s][3] = fmaf(sw, e3.w, racc[s][3]);
            }
        }

        // ---- phase C: layer 3 + trace + reduce + store ----
#pragma unroll
        for (int s = 0; s < NS; s++) {
            float od[8] = {0.f, 0.f, 0.f, 0.f, 0.f, 0.f, 0.f, 0.f};
            float tr = 0.f;
#pragma unroll
            for (int k = 0; k < 4; k++) {
                float h2 = tanhf(bacc[s][k]);
                float s2v = 1.0f - h2 * h2;
                tr = fmaf(s2v, racc[s][k], tr);
                int j = lane + 32 * k;
                float4 lo = *(const float4*)&W3s[j * 8];
                float4 hi = *(const float4*)&W3s[j * 8 + 4];
                od[0] = fmaf(h2, lo.x, od[0]);
                od[1] = fmaf(h2, lo.y, od[1]);
                od[2] = fmaf(h2, lo.z, od[2]);
                od[3] = fmaf(h2, lo.w, od[3]);
                od[4] = fmaf(h2, hi.x, od[4]);
                od[5] = fmaf(h2, hi.y, od[5]);
                od[6] = fmaf(h2, hi.z, od[6]);
                od[7] = fmaf(h2, hi.w, od[7]);
            }
#pragma unroll
            for (int off = 16; off; off >>= 1) {
#pragma unroll
                for (int m = 0; m < 8; m++)
                    od[m] += __shfl_xor_sync(0xffffffffu, od[m], off);
                tr += __shfl_xor_sync(0xffffffffu, tr, off);
            }
            if (lane == 0) {
                float* o = out + (size_t)(s0 + s) * Dd;
                float4 v0 = make_float4(od[0] + b3s[0], od[1] + b3s[1],
                                        od[2] + b3s[2], od[3] + b3s[3]);
                float4 v1 = make_float4(od[4] + b3s[4], od[5] + b3s[5],
                                        od[6] + b3s[6], od[7] + b3s[7]);
                *(float4*)o = v0;
                *(float4*)(o + 4) = v1;
                out[(size_t)B * Dd + (s0 + s)] = -tr;
            }
        }
        __syncwarp();
    }
}

extern "C" void kernel_launch(void* const* d_in, const int* in_sizes, int n_in,
                              void* d_out, int out_size) {
    const float* z  = (const float*)d_in[0];
    // d_in[1] = logp_z (unused by reference output)
    const float* t  = (const float*)d_in[2];
    const float* W1 = (const float*)d_in[3];
    const float* b1 = (const float*)d_in[4];
    const float* W2 = (const float*)d_in[5];
    const float* b2 = (const float*)d_in[6];
    const float* W3 = (const float*)d_in[7];
    const float* b3 = (const float*)d_in[8];
    float* out = (float*)d_out;
    int B = in_sizes[0] / Dd;

    cudaFuncSetAttribute(cnf_main, cudaFuncAttributeMaxDynamicSharedMemorySize,
                         SMEM_BYTES);

    prep_E<<<(Hh * Hh + 255) / 256, 256>>>(W1, W2, W3);
    cnf_main<<<NBLK, THREADS, SMEM_BYTES>>>(z, t, W1, b1, W2, b2, W3, b3, out, B);
}

// round 4
// speedup vs baseline: 1.3074x; 1.3074x over previous
#include <cuda_runtime.h>

// CNF_plain: z[B,8], t scalar; MLP 9->128->128->8 with tanh; outputs
// dz_dt [B,8] and dlogp = -trace(J) [B,1], packed as [B*8 dz | B dlogp].
//
// trace = s1^T E s2 with E = W2 .* (W1[:D,:]^T W3^T), s1=1-h1^2, s2=1-h2^2.
// E precomputed per launch by prep_E.
//
// R4: packed fp32x2 (FFMA2) phase B. Samples paired: smem h stored as
// (h[2p],h[2p+1]) pairs; accumulators are f32x2; weights duplicated via
// mov.b64 on the alu pipe. 16 warps/block, NS=8 (4 pairs), unroll 1.

#define Hh 128
#define Dd 8
#define NW 16          // warps per block
#define NS 8           // samples per warp per group
#define NP (NS / 2)    // sample pairs
#define THREADS (NW * 32)
#define NBLK 152

typedef unsigned long long u64;

__device__ __forceinline__ u64 pk2(float lo, float hi) {
    u64 r; asm("mov.b64 %0,{%1,%2};" : "=l"(r) : "f"(lo), "f"(hi)); return r;
}
__device__ __forceinline__ void upk2(float& lo, float& hi, u64 v) {
    asm("mov.b64 {%0,%1},%2;" : "=f"(lo), "=f"(hi) : "l"(v));
}
__device__ __forceinline__ u64 dup2(float x) { return pk2(x, x); }
__device__ __forceinline__ void fma2(u64& d, u64 a, u64 b) {
    asm("fma.rn.f32x2 %0,%1,%2,%0;" : "+l"(d) : "l"(a), "l"(b));
}

// E in lane-permuted layout: p(i,j) = i*128 + (j&31)*4 + (j>>5)
__device__ float g_Ep[Hh * Hh];

__global__ void prep_E(const float* __restrict__ W1,
                       const float* __restrict__ W2,
                       const float* __restrict__ W3) {
    int idx = blockIdx.x * blockDim.x + threadIdx.x;   // 0..16383
    if (idx >= Hh * Hh) return;
    int i = idx >> 7, j = idx & 127;
    float c = 0.f;
#pragma unroll
    for (int d = 0; d < Dd; d++)
        c = fmaf(W1[d * Hh + i], W3[j * Dd + d], c);
    g_Ep[(i << 7) + ((j & 31) << 2) + (j >> 5)] = W2[i * Hh + j] * c;
}

// smem layout (floats):
//  hp        : NW*NP*128 u64 = 16384 floats (h sample-pairs)
//  W2s       : 16384 (permuted)
//  Es        : 16384 (permuted, from g_Ep)
//  W1s       : 9*128 (permuted)
//  W3s       : 128*8
//  b1s,b2s   : 128 each
//  b3s       : 8
#define SMEM_FLOATS (16384 * 3 + 9 * 128 + 128 * 8 + 128 + 128 + 8)
#define SMEM_BYTES (SMEM_FLOATS * 4)

__global__ __launch_bounds__(THREADS, 1)
void cnf_main(const float* __restrict__ z, const float* __restrict__ tptr,
              const float* __restrict__ W1, const float* __restrict__ b1,
              const float* __restrict__ W2, const float* __restrict__ b2,
              const float* __restrict__ W3, const float* __restrict__ b3,
              float* __restrict__ out, int B) {
    extern __shared__ float smem[];
    u64*   hp  = (u64*)smem;                   // [NW][NP][128]
    float* W2s = smem + NW * NP * Hh * 2;
    float* Es  = W2s + 16384;
    float* W1s = Es + 16384;
    float* W3s = W1s + 9 * Hh;
    float* b1s = W3s + Hh * Dd;
    float* b2s = b1s + Hh;
    float* b3s = b2s + Hh;

    // ---- stage weights into SMEM ----
    for (int idx = threadIdx.x; idx < Hh * Hh; idx += THREADS) {
        int i = idx >> 7, j = idx & 127;
        int p = (i << 7) + ((j & 31) << 2) + (j >> 5);
        W2s[p]  = W2[idx];
        Es[idx] = g_Ep[idx];                   // already permuted
    }
    for (int idx = threadIdx.x; idx < 9 * Hh; idx += THREADS) {
        int i = idx >> 7, j = idx & 127;
        W1s[(i << 7) + ((j & 31) << 2) + (j >> 5)] = W1[idx];
    }
    for (int idx = threadIdx.x; idx < Hh * Dd; idx += THREADS)
        W3s[idx] = W3[idx];
    if (threadIdx.x < Hh) {
        b1s[threadIdx.x] = b1[threadIdx.x];
        b2s[threadIdx.x] = b2[threadIdx.x];
    }
    if (threadIdx.x < Dd) b3s[threadIdx.x] = b3[threadIdx.x];
    __syncthreads();

    const int wid = threadIdx.x >> 5;
    const int lane = threadIdx.x & 31;
    u64* myhp = hp + (wid * NP) * Hh;          // [NP][128]
    const float t = tptr[0];
    const u64 ones = pk2(1.0f, 1.0f);
    const u64 SGN  = 0x8000000080000000ULL;

    const int nGroups = B / NS;
    const int warpGlobal = blockIdx.x * NW + wid;
    const int totalWarps = gridDim.x * NW;

    for (int g = warpGlobal; g < nGroups; g += totalWarps) {
        const int s0 = g * NS;

        // ---- phase A: layer 1 (9 -> 128), scalar ----
        float zreg[NS];
#pragma unroll
        for (int s = 0; s < NS; s++)
            zreg[s] = (lane < Dd) ? z[(size_t)(s0 + s) * Dd + lane] : t;

        float a[NS][4];
#pragma unroll
        for (int s = 0; s < NS; s++)
#pragma unroll
            for (int k = 0; k < 4; k++)
                a[s][k] = b1s[lane + 32 * k];

#pragma unroll
        for (int i = 0; i < 9; i++) {
            float4 w = *(const float4*)&W1s[(i << 7) + (lane << 2)];
#pragma unroll
            for (int s = 0; s < NS; s++) {
                float xi = __shfl_sync(0xffffffffu, zreg[s], i);
                a[s][0] = fmaf(xi, w.x, a[s][0]);
                a[s][1] = fmaf(xi, w.y, a[s][1]);
                a[s][2] = fmaf(xi, w.z, a[s][2]);
                a[s][3] = fmaf(xi, w.w, a[s][3]);
            }
        }

        __syncwarp();
#pragma unroll
        for (int p = 0; p < NP; p++)
#pragma unroll
            for (int k = 0; k < 4; k++)
                myhp[p * Hh + lane + 32 * k] =
                    pk2(tanhf(a[2 * p][k]), tanhf(a[2 * p + 1][k]));
        __syncwarp();

        // ---- phase B: packed GEMVs  b = h1@W2+b2,  r = (1-h1^2)@E ----
        u64 bacc[NP][4], racc[NP][4];
#pragma unroll
        for (int p = 0; p < NP; p++)
#pragma unroll
            for (int k = 0; k < 4; k++) {
                bacc[p][k] = dup2(b2s[lane + 32 * k]);
                racc[p][k] = 0ULL;
            }

#pragma unroll 1
        for (int i = 0; i < Hh; i++) {
            float4 w = *(const float4*)&W2s[(i << 7) + (lane << 2)];
            float4 e = *(const float4*)&Es[(i << 7) + (lane << 2)];
            u64 wd0 = dup2(w.x), wd1 = dup2(w.y), wd2 = dup2(w.z), wd3 = dup2(w.w);
            u64 ed0 = dup2(e.x), ed1 = dup2(e.y), ed2 = dup2(e.z), ed3 = dup2(e.w);
#pragma unroll
            for (int p = 0; p < NP; p++) {
                u64 h2 = myhp[p * Hh + i];
                u64 nh = h2 ^ SGN;
                u64 s2 = ones;
                fma2(s2, nh, h2);              // s2 = 1 - h^2 (packed)
                fma2(bacc[p][0], h2, wd0);
                fma2(bacc[p][1], h2, wd1);
                fma2(bacc[p][2], h2, wd2);
                fma2(bacc[p][3], h2, wd3);
                fma2(racc[p][0], s2, ed0);
                fma2(racc[p][1], s2, ed1);
                fma2(racc[p][2], s2, ed2);
                fma2(racc[p][3], s2, ed3);
            }
        }

        // ---- phase C: layer 3 + trace + reduce + store ----
#pragma unroll
        for (int s = 0; s < NS; s++) {
            float od[8] = {0.f, 0.f, 0.f, 0.f, 0.f, 0.f, 0.f, 0.f};
            float tr = 0.f;
#pragma unroll
            for (int k = 0; k < 4; k++) {
                float blo, bhi, rlo, rhi;
                upk2(blo, bhi, bacc[s >> 1][k]);
                upk2(rlo, rhi, racc[s >> 1][k]);
                float bv = (s & 1) ? bhi : blo;
                float rv = (s & 1) ? rhi : rlo;
                float h2 = tanhf(bv);
                float s2v = 1.0f - h2 * h2;
                tr = fmaf(s2v, rv, tr);
                int j = lane + 32 * k;
                float4 lo = *(const float4*)&W3s[j * 8];
                float4 hi = *(const float4*)&W3s[j * 8 + 4];
                od[0] = fmaf(h2, lo.x, od[0]);
                od[1] = fmaf(h2, lo.y, od[1]);
                od[2] = fmaf(h2, lo.z, od[2]);
                od[3] = fmaf(h2, lo.w, od[3]);
                od[4] = fmaf(h2, hi.x, od[4]);
                od[5] = fmaf(h2, hi.y, od[5]);
                od[6] = fmaf(h2, hi.z, od[6]);
                od[7] = fmaf(h2, hi.w, od[7]);
            }
#pragma unroll
            for (int off = 16; off; off >>= 1) {
#pragma unroll
                for (int m = 0; m < 8; m++)
                    od[m] += __shfl_xor_sync(0xffffffffu, od[m], off);
                tr += __shfl_xor_sync(0xffffffffu, tr, off);
            }
            if (lane == 0) {
                float* o = out + (size_t)(s0 + s) * Dd;
                float4 v0 = make_float4(od[0] + b3s[0], od[1] + b3s[1],
                                        od[2] + b3s[2], od[3] + b3s[3]);
                float4 v1 = make_float4(od[4] + b3s[4], od[5] + b3s[5],
                                        od[6] + b3s[6], od[7] + b3s[7]);
                *(float4*)o = v0;
                *(float4*)(o + 4) = v1;
                out[(size_t)B * Dd + (s0 + s)] = -tr;
            }
        }
        __syncwarp();
    }
}

extern "C" void kernel_launch(void* const* d_in, const int* in_sizes, int n_in,
                              void* d_out, int out_size) {
    const float* z  = (const float*)d_in[0];
    // d_in[1] = logp_z (unused by reference output)
    const float* t  = (const float*)d_in[2];
    const float* W1 = (const float*)d_in[3];
    const float* b1 = (const float*)d_in[4];
    const float* W2 = (const float*)d_in[5];
    const float* b2 = (const float*)d_in[6];
    const float* W3 = (const float*)d_in[7];
    const float* b3 = (const float*)d_in[8];
    float* out = (float*)d_out;
    int B = in_sizes[0] / Dd;

    cudaFuncSetAttribute(cnf_main, cudaFuncAttributeMaxDynamicSharedMemorySize,
                         SMEM_BYTES);

    prep_E<<<(Hh * Hh + 255) / 256, 256>>>(W1, W2, W3);
    cnf_main<<<NBLK, THREADS, SMEM_BYTES>>>(z, t, W1, b1, W2, b2, W3, b3, out, B);
}

// round 6
// speedup vs baseline: 1.4163x; 1.0833x over previous
#include <cuda_runtime.h>
#include <cuda_bf16.h>
#include <cstdint>

// CNF_plain via legacy HMMA (mma.sync m16n8k16 bf16, fp32 accum):
//   bacc = h @ W2,  racc = s1 @ E,  E = W2 .* (W1[:8,:]^T W3^T)
// bf16x3 compensation: Ahi@Bhi + Alo@Bhi + Ahi@Blo (per GEMM).
// Epilogue: h2=tanh(bacc+b2), s2=1-h2^2, tr=sum s2*racc, dz=h2@W3+b3.
// NOTE: tcgen05 is NOT available (harness targets compute_103, no 'a').

#define Hh 128
#define Dd 8
#define THREADS 256
#define NBLK 148
#define TILE_M 64

// padded strides: 136 bf16 = 68 u32 per row (conflict-free frags)
#define ASTR 68
#define BSTR 68

// SMEM byte offsets
#define SM_AHH 0
#define SM_AHL 17408
#define SM_ASH 34816
#define SM_ASL 52224
#define SM_BWH 69632
#define SM_BWL 104448
#define SM_BEH 139264
#define SM_BEL 174080
#define SM_W1  208896
#define SM_W3  213504
#define SM_B1  217600
#define SM_B2  218112
#define SM_B3  218624
#define SM_PART 218688
#define SM_TOTAL 220992

static __device__ unsigned short g_bwh[16384];  // [j][i] = bf16_hi(W2[i,j])
static __device__ unsigned short g_bwl[16384];
static __device__ unsigned short g_beh[16384];  // [j][i] = bf16_hi(E[i,j])
static __device__ unsigned short g_bel[16384];

__global__ void prep(const float* __restrict__ W1, const float* __restrict__ W2,
                     const float* __restrict__ W3) {
    int idx = blockIdx.x * blockDim.x + threadIdx.x;
    if (idx >= 16384) return;
    int j = idx >> 7, i = idx & 127;
    float c = 0.f;
#pragma unroll
    for (int d = 0; d < Dd; d++) c = fmaf(W1[d * Hh + i], W3[j * Dd + d], c);
    float w2 = W2[i * Hh + j];
    float e  = w2 * c;
    __nv_bfloat16 h;
    h = __float2bfloat16(w2);
    g_bwh[idx] = __bfloat16_as_ushort(h);
    g_bwl[idx] = __bfloat16_as_ushort(__float2bfloat16(w2 - __bfloat162float(h)));
    h = __float2bfloat16(e);
    g_beh[idx] = __bfloat16_as_ushort(h);
    g_bel[idx] = __bfloat16_as_ushort(__float2bfloat16(e - __bfloat162float(h)));
}

__device__ __forceinline__ float ftanh(float x) {
    float ax = fabsf(x);
    float t = __expf(-2.0f * ax);
    float r = (1.0f - t) * __frcp_rn(1.0f + t);
    return copysignf(r, x);
}

__device__ __forceinline__ uint32_t pkhi(float a, float b, float& ra, float& rb) {
    __nv_bfloat16 ha = __float2bfloat16(a), hb = __float2bfloat16(b);
    ra = a - __bfloat162float(ha);
    rb = b - __bfloat162float(hb);
    return ((uint32_t)__bfloat16_as_ushort(hb) << 16) | __bfloat16_as_ushort(ha);
}
__device__ __forceinline__ uint32_t pk2b(float a, float b) {
    __nv_bfloat16 ha = __float2bfloat16(a), hb = __float2bfloat16(b);
    return ((uint32_t)__bfloat16_as_ushort(hb) << 16) | __bfloat16_as_ushort(ha);
}

__device__ __forceinline__ void mma16816(float* c, const uint32_t* a,
                                         const uint32_t* b) {
    asm volatile(
        "mma.sync.aligned.m16n8k16.row.col.f32.bf16.bf16.f32 "
        "{%0,%1,%2,%3}, {%4,%5,%6,%7}, {%8,%9}, {%0,%1,%2,%3};"
        : "+f"(c[0]), "+f"(c[1]), "+f"(c[2]), "+f"(c[3])
        : "r"(a[0]), "r"(a[1]), "r"(a[2]), "r"(a[3]), "r"(b[0]), "r"(b[1]));
}

__global__ __launch_bounds__(THREADS, 1)
void cnf_mma(const float* __restrict__ z, const float* __restrict__ tptr,
             const float* __restrict__ W1, const float* __restrict__ b1,
             const float* __restrict__ b2,
             const float* __restrict__ W3, const float* __restrict__ b3,
             float* __restrict__ out, int B) {
    extern __shared__ char smem[];
    uint32_t* Ahh = (uint32_t*)(smem + SM_AHH);
    uint32_t* Ahl = (uint32_t*)(smem + SM_AHL);
    uint32_t* Ash = (uint32_t*)(smem + SM_ASH);
    uint32_t* Asl = (uint32_t*)(smem + SM_ASL);
    uint32_t* Bwh = (uint32_t*)(smem + SM_BWH);
    uint32_t* Bwl = (uint32_t*)(smem + SM_BWL);
    uint32_t* Beh = (uint32_t*)(smem + SM_BEH);
    uint32_t* Bel = (uint32_t*)(smem + SM_BEL);
    float* W1s = (float*)(smem + SM_W1);
    float* W3s = (float*)(smem + SM_W3);
    float* b1s = (float*)(smem + SM_B1);
    float* b2s = (float*)(smem + SM_B2);
    float* b3s = (float*)(smem + SM_B3);
    float* part = (float*)(smem + SM_PART);

    const int tid = threadIdx.x;
    const int wid = tid >> 5, lane = tid & 31;
    const int wgid = wid >> 2;         // N-half: j in [wgid*64, +64)
    const int wsub = wid & 3;          // sample row-tile (16 rows)
    const int lq = lane & 3, lr = lane >> 2;

    // ---- stage B planes (pad 128 -> 136 bf16 per row) ----
    {
        const uint4* s0 = (const uint4*)g_bwh;
        const uint4* s1 = (const uint4*)g_bwl;
        const uint4* s2 = (const uint4*)g_beh;
        const uint4* s3 = (const uint4*)g_bel;
        uint4* d0 = (uint4*)Bwh; uint4* d1 = (uint4*)Bwl;
        uint4* d2 = (uint4*)Beh; uint4* d3 = (uint4*)Bel;
        for (int k = tid; k < 2048; k += THREADS) {
            int j = k >> 4, c = k & 15;
            int dsti = j * 17 + c;
            d0[dsti] = s0[k]; d1[dsti] = s1[k];
            d2[dsti] = s2[k]; d3[dsti] = s3[k];
        }
    }
    for (int k = tid; k < 9 * Hh; k += THREADS) W1s[k] = W1[k];
    for (int k = tid; k < Hh * Dd; k += THREADS) W3s[k] = W3[k];
    if (tid < Hh) { b1s[tid] = b1[tid]; b2s[tid] = b2[tid]; }
    if (tid < Dd) b3s[tid] = b3[tid];
    __syncthreads();

    const float t = tptr[0];
    const int m = tid >> 2;            // phase-A sample (0..63)
    const int iq = tid & 3;            // phase-A i-quarter

    const int nTiles = B / TILE_M;
    for (int tile = blockIdx.x; tile < nTiles; tile += gridDim.x) {
        // ================= phase A: layer 1 + split planes =================
        {
            const int mg = tile * TILE_M + m;
            float4 z0 = *(const float4*)(z + (size_t)mg * 8);
            float4 z1 = *(const float4*)(z + (size_t)mg * 8 + 4);
            float zv[8] = {z0.x, z0.y, z0.z, z0.w, z1.x, z1.y, z1.z, z1.w};
#pragma unroll
            for (int c8 = 0; c8 < 8; c8++) {
                int i0 = iq * 32 + c8 * 4;
                float4 acc = *(const float4*)(b1s + i0);
                float4 wt = *(const float4*)(W1s + 8 * Hh + i0);
                acc.x = fmaf(t, wt.x, acc.x); acc.y = fmaf(t, wt.y, acc.y);
                acc.z = fmaf(t, wt.z, acc.z); acc.w = fmaf(t, wt.w, acc.w);
#pragma unroll
                for (int d = 0; d < 8; d++) {
                    float4 w = *(const float4*)(W1s + d * Hh + i0);
                    acc.x = fmaf(zv[d], w.x, acc.x);
                    acc.y = fmaf(zv[d], w.y, acc.y);
                    acc.z = fmaf(zv[d], w.z, acc.z);
                    acc.w = fmaf(zv[d], w.w, acc.w);
                }
                float h0 = ftanh(acc.x), h1 = ftanh(acc.y);
                float h2 = ftanh(acc.z), h3 = ftanh(acc.w);
                float s0 = fmaf(-h0, h0, 1.f), s1v = fmaf(-h1, h1, 1.f);
                float s2 = fmaf(-h2, h2, 1.f), s3 = fmaf(-h3, h3, 1.f);
                float r0, r1, r2, r3, q0, q1, q2, q3;
                uint32_t hh01 = pkhi(h0, h1, r0, r1);
                uint32_t hh23 = pkhi(h2, h3, r2, r3);
                uint32_t sh01 = pkhi(s0, s1v, q0, q1);
                uint32_t sh23 = pkhi(s2, s3, q2, q3);
                int o = m * ASTR + iq * 16 + c8 * 2;
                *(uint2*)&Ahh[o] = make_uint2(hh01, hh23);
                *(uint2*)&Ahl[o] = make_uint2(pk2b(r0, r1), pk2b(r2, r3));
                *(uint2*)&Ash[o] = make_uint2(sh01, sh23);
                *(uint2*)&Asl[o] = make_uint2(pk2b(q0, q1), pk2b(q2, q3));
            }
        }
        __syncthreads();

        // ================= phase B: HMMA =================
        float cb[8][4], cr[8][4];
#pragma unroll
        for (int nt = 0; nt < 8; nt++)
#pragma unroll
            for (int q = 0; q < 4; q++) { cb[nt][q] = 0.f; cr[nt][q] = 0.f; }

#pragma unroll 1
        for (int kt = 0; kt < 8; kt++) {
            const int ra = (wsub * 16 + lr) * ASTR + kt * 8 + lq;
            uint32_t ah[4], al[4], sh[4], sl[4];
            ah[0] = Ahh[ra];           ah[1] = Ahh[ra + 8 * ASTR];
            ah[2] = Ahh[ra + 4];       ah[3] = Ahh[ra + 8 * ASTR + 4];
            al[0] = Ahl[ra];           al[1] = Ahl[ra + 8 * ASTR];
            al[2] = Ahl[ra + 4];       al[3] = Ahl[ra + 8 * ASTR + 4];
            sh[0] = Ash[ra];           sh[1] = Ash[ra + 8 * ASTR];
            sh[2] = Ash[ra + 4];       sh[3] = Ash[ra + 8 * ASTR + 4];
            sl[0] = Asl[ra];           sl[1] = Asl[ra + 8 * ASTR];
            sl[2] = Asl[ra + 4];       sl[3] = Asl[ra + 8 * ASTR + 4];
#pragma unroll
            for (int nt = 0; nt < 8; nt++) {
                const int nb = (wgid * 64 + nt * 8 + lr) * BSTR + kt * 8 + lq;
                uint32_t bw0[2] = {Bwh[nb], Bwh[nb + 4]};
                uint32_t bw1[2] = {Bwl[nb], Bwl[nb + 4]};
                uint32_t be0[2] = {Beh[nb], Beh[nb + 4]};
                uint32_t be1[2] = {Bel[nb], Bel[nb + 4]};
                mma16816(cb[nt], ah, bw0);
                mma16816(cr[nt], sh, be0);
                mma16816(cb[nt], al, bw0);
                mma16816(cr[nt], sl, be0);
                mma16816(cb[nt], ah, bw1);
                mma16816(cr[nt], sh, be1);
            }
        }

        // ================= epilogue =================
        float odA[2][8], trA[2];
#pragma unroll
        for (int rh = 0; rh < 2; rh++) {
            float od[8] = {0.f, 0.f, 0.f, 0.f, 0.f, 0.f, 0.f, 0.f};
            float tr = 0.f;
#pragma unroll
            for (int nt = 0; nt < 8; nt++) {
#pragma unroll
                for (int q = 0; q < 2; q++) {
                    int j = wgid * 64 + nt * 8 + lq * 2 + q;
                    float bv = cb[nt][rh * 2 + q] + b2s[j];
                    float h2 = ftanh(bv);
                    float s2v = fmaf(-h2, h2, 1.0f);
                    tr = fmaf(s2v, cr[nt][rh * 2 + q], tr);
                    float4 lo = *(const float4*)&W3s[j * 8];
                    float4 hi = *(const float4*)&W3s[j * 8 + 4];
                    od[0] = fmaf(h2, lo.x, od[0]);
                    od[1] = fmaf(h2, lo.y, od[1]);
                    od[2] = fmaf(h2, lo.z, od[2]);
                    od[3] = fmaf(h2, lo.w, od[3]);
                    od[4] = fmaf(h2, hi.x, od[4]);
                    od[5] = fmaf(h2, hi.y, od[5]);
                    od[6] = fmaf(h2, hi.z, od[6]);
                    od[7] = fmaf(h2, hi.w, od[7]);
                }
            }
#pragma unroll
            for (int off = 1; off <= 2; off <<= 1) {
#pragma unroll
                for (int k = 0; k < 8; k++)
                    od[k] += __shfl_xor_sync(0xffffffffu, od[k], off);
                tr += __shfl_xor_sync(0xffffffffu, tr, off);
            }
#pragma unroll
            for (int k = 0; k < 8; k++) odA[rh][k] = od[k];
            trA[rh] = tr;
        }

        if (wgid == 1 && lq == 0) {
#pragma unroll
            for (int rh = 0; rh < 2; rh++) {
                int mr = wsub * 16 + lr + rh * 8;
                float* pp = part + mr * 9;
#pragma unroll
                for (int k = 0; k < 8; k++) pp[k] = odA[rh][k];
                pp[8] = trA[rh];
            }
        }
        __syncthreads();
        if (wgid == 0 && lq == 0) {
#pragma unroll
            for (int rh = 0; rh < 2; rh++) {
                int mr = wsub * 16 + lr + rh * 8;
                const float* pp = part + mr * 9;
                int mg = tile * TILE_M + mr;
                float* o = out + (size_t)mg * 8;
                float4 v0 = make_float4(odA[rh][0] + pp[0] + b3s[0],
                                        odA[rh][1] + pp[1] + b3s[1],
                                        odA[rh][2] + pp[2] + b3s[2],
                                        odA[rh][3] + pp[3] + b3s[3]);
                float4 v1 = make_float4(odA[rh][4] + pp[4] + b3s[4],
                                        odA[rh][5] + pp[5] + b3s[5],
                                        odA[rh][6] + pp[6] + b3s[6],
                                        odA[rh][7] + pp[7] + b3s[7]);
                *(float4*)o = v0;
                *(float4*)(o + 4) = v1;
                out[(size_t)B * 8 + mg] = -(trA[rh] + pp[8]);
            }
        }
        __syncthreads();
    }
}

extern "C" void kernel_launch(void* const* d_in, const int* in_sizes, int n_in,
                              void* d_out, int out_size) {
    const float* z  = (const float*)d_in[0];
    // d_in[1] = logp_z (unused by reference output)
    const float* t  = (const float*)d_in[2];
    const float* W1 = (const float*)d_in[3];
    const float* b1 = (const float*)d_in[4];
    const float* W2 = (const float*)d_in[5];
    const float* b2 = (const float*)d_in[6];
    const float* W3 = (const float*)d_in[7];
    const float* b3 = (const float*)d_in[8];
    float* out = (float*)d_out;
    int B = in_sizes[0] / Dd;

    cudaFuncSetAttribute(cnf_mma, cudaFuncAttributeMaxDynamicSharedMemorySize,
                         SM_TOTAL);

    prep<<<64, 256>>>(W1, W2, W3);
    cnf_mma<<<NBLK, THREADS, SM_TOTAL>>>(z, t, W1, b1, b2, W3, b3, out, B);
}

// round 9
// speedup vs baseline: 1.4452x; 1.0204x over previous
#include <cuda_runtime.h>
#include <cuda_bf16.h>
#include <cstdint>

// CNF_plain via HMMA (mma.sync m16n8k16 bf16, fp32 accum):
//   bacc = h @ W2,  racc = s1 @ E,  E = W2 .* (W1[:8,:]^T W3^T)
// bf16x3 compensation: Ahi@Bhi + Alo@Bhi + Ahi@Blo (per GEMM).
// Epilogue: h2=tanh(bacc+b2), s2=1-h2^2, tr=sum s2*racc, dz=h2@W3+b3.
// R8: ldmatrix fragment loads; B uses NON-trans ldmatrix ([n][k] row-major
// already matches the row.col B fragment: k-pair in register, n=lane>>2).

#define Hh 128
#define Dd 8
#define THREADS 256
#define NBLK 148
#define TILE_M 64

// padded strides: 136 bf16 = 68 u32 per row
#define ASTR 68
#define BSTR 68

// SMEM byte offsets
#define SM_AHH 0
#define SM_AHL 17408
#define SM_ASH 34816
#define SM_ASL 52224
#define SM_BWH 69632
#define SM_BWL 104448
#define SM_BEH 139264
#define SM_BEL 174080
#define SM_W1  208896
#define SM_W3  213504
#define SM_B1  217600
#define SM_B2  218112
#define SM_B3  218624
#define SM_PART 218688
#define SM_TOTAL 220992

static __device__ unsigned short g_bwh[16384];  // [j][i] = bf16_hi(W2[i,j])
static __device__ unsigned short g_bwl[16384];
static __device__ unsigned short g_beh[16384];  // [j][i] = bf16_hi(E[i,j])
static __device__ unsigned short g_bel[16384];

__global__ void prep(const float* __restrict__ W1, const float* __restrict__ W2,
                     const float* __restrict__ W3) {
    int idx = blockIdx.x * blockDim.x + threadIdx.x;
    if (idx >= 16384) return;
    int j = idx >> 7, i = idx & 127;
    float c = 0.f;
#pragma unroll
    for (int d = 0; d < Dd; d++) c = fmaf(W1[d * Hh + i], W3[j * Dd + d], c);
    float w2 = W2[i * Hh + j];
    float e  = w2 * c;
    __nv_bfloat16 h;
    h = __float2bfloat16(w2);
    g_bwh[idx] = __bfloat16_as_ushort(h);
    g_bwl[idx] = __bfloat16_as_ushort(__float2bfloat16(w2 - __bfloat162float(h)));
    h = __float2bfloat16(e);
    g_beh[idx] = __bfloat16_as_ushort(h);
    g_bel[idx] = __bfloat16_as_ushort(__float2bfloat16(e - __bfloat162float(h)));
}

__device__ __forceinline__ float ftanh(float x) {
    float ax = fabsf(x);
    float t = __expf(-2.0f * ax);
    float r = (1.0f - t) * __frcp_rn(1.0f + t);
    return copysignf(r, x);
}

__device__ __forceinline__ uint32_t pkhi(float a, float b, float& ra, float& rb) {
    __nv_bfloat16 ha = __float2bfloat16(a), hb = __float2bfloat16(b);
    ra = a - __bfloat162float(ha);
    rb = b - __bfloat162float(hb);
    return ((uint32_t)__bfloat16_as_ushort(hb) << 16) | __bfloat16_as_ushort(ha);
}
__device__ __forceinline__ uint32_t pk2b(float a, float b) {
    __nv_bfloat16 ha = __float2bfloat16(a), hb = __float2bfloat16(b);
    return ((uint32_t)__bfloat16_as_ushort(hb) << 16) | __bfloat16_as_ushort(ha);
}

__device__ __forceinline__ void mma16816(float* c, const uint32_t* a,
                                         const uint32_t* b) {
    asm volatile(
        "mma.sync.aligned.m16n8k16.row.col.f32.bf16.bf16.f32 "
        "{%0,%1,%2,%3}, {%4,%5,%6,%7}, {%8,%9}, {%0,%1,%2,%3};"
        : "+f"(c[0]), "+f"(c[1]), "+f"(c[2]), "+f"(c[3])
        : "r"(a[0]), "r"(a[1]), "r"(a[2]), "r"(a[3]), "r"(b[0]), "r"(b[1]));
}

__device__ __forceinline__ void ldsm4(uint32_t* r, uint32_t a) {
    asm volatile("ldmatrix.sync.aligned.m8n8.x4.shared.b16 {%0,%1,%2,%3},[%4];"
                 : "=r"(r[0]), "=r"(r[1]), "=r"(r[2]), "=r"(r[3]) : "r"(a));
}

__device__ __forceinline__ uint32_t s2u(const void* p) {
    uint32_t a;
    asm("{.reg .u64 t; cvta.to.shared.u64 t, %1; cvt.u32.u64 %0, t;}"
        : "=r"(a) : "l"(p));
    return a;
}

__global__ __launch_bounds__(THREADS, 1)
void cnf_mma(const float* __restrict__ z, const float* __restrict__ tptr,
             const float* __restrict__ W1, const float* __restrict__ b1,
             const float* __restrict__ b2,
             const float* __restrict__ W3, const float* __restrict__ b3,
             float* __restrict__ out, int B) {
    extern __shared__ char smem[];
    uint32_t* Ahh = (uint32_t*)(smem + SM_AHH);
    uint32_t* Ahl = (uint32_t*)(smem + SM_AHL);
    uint32_t* Ash = (uint32_t*)(smem + SM_ASH);
    uint32_t* Asl = (uint32_t*)(smem + SM_ASL);
    float* W1s = (float*)(smem + SM_W1);
    float* W3s = (float*)(smem + SM_W3);
    float* b1s = (float*)(smem + SM_B1);
    float* b2s = (float*)(smem + SM_B2);
    float* b3s = (float*)(smem + SM_B3);
    float* part = (float*)(smem + SM_PART);

    const int tid = threadIdx.x;
    const int wid = tid >> 5, lane = tid & 31;
    const int wgid = wid >> 2;         // N-half: j in [wgid*64, +64)
    const int wsub = wid & 3;          // sample row-tile (16 rows)
    const int lq = lane & 3, lr = lane >> 2;

    // ---- stage B planes (pad 128 -> 136 bf16 per row) ----
    {
        const uint4* s0 = (const uint4*)g_bwh;
        const uint4* s1 = (const uint4*)g_bwl;
        const uint4* s2 = (const uint4*)g_beh;
        const uint4* s3 = (const uint4*)g_bel;
        uint4* d0 = (uint4*)(smem + SM_BWH);
        uint4* d1 = (uint4*)(smem + SM_BWL);
        uint4* d2 = (uint4*)(smem + SM_BEH);
        uint4* d3 = (uint4*)(smem + SM_BEL);
        for (int k = tid; k < 2048; k += THREADS) {
            int j = k >> 4, c = k & 15;
            int dsti = j * 17 + c;
            d0[dsti] = s0[k]; d1[dsti] = s1[k];
            d2[dsti] = s2[k]; d3[dsti] = s3[k];
        }
    }
    for (int k = tid; k < 9 * Hh; k += THREADS) W1s[k] = W1[k];
    for (int k = tid; k < Hh * Dd; k += THREADS) W3s[k] = W3[k];
    if (tid < Hh) { b1s[tid] = b1[tid]; b2s[tid] = b2[tid]; }
    if (tid < Dd) b3s[tid] = b3[tid];
    __syncthreads();

    const float t = tptr[0];
    const int m = tid >> 2;            // phase-A sample (0..63)
    const int iq = tid & 3;            // phase-A i-quarter

    // ---- ldmatrix per-thread byte offsets ----
    const int grp = lane >> 3, l7 = lane & 7;
    // A frag: grp0:(m+0,k+0) grp1:(m+8,k+0) grp2:(m+0,k+8) grp3:(m+8,k+8)
    const uint32_t aoff =
        (uint32_t)(((wsub * 16 + l7 + (grp & 1) * 8) * ASTR + (grp >> 1) * 4) * 4);
    // B frag (non-trans): grp0:(n+0,k+0) grp1:(n+0,k+8) grp2:(n+8,k+0) grp3:(n+8,k+8)
    const uint32_t boff =
        (uint32_t)(((wgid * 64 + l7 + (grp >> 1) * 8) * BSTR + (grp & 1) * 4) * 4);
    const uint32_t sAhh = s2u(Ahh) + aoff, sAhl = s2u(Ahl) + aoff;
    const uint32_t sAsh = s2u(Ash) + aoff, sAsl = s2u(Asl) + aoff;
    const uint32_t sBwh = s2u(smem + SM_BWH) + boff;
    const uint32_t sBwl = s2u(smem + SM_BWL) + boff;
    const uint32_t sBeh = s2u(smem + SM_BEH) + boff;
    const uint32_t sBel = s2u(smem + SM_BEL) + boff;

    const int nTiles = B / TILE_M;
    for (int tile = blockIdx.x; tile < nTiles; tile += gridDim.x) {
        // ================= phase A: layer 1 + split planes =================
        {
            const int mg = tile * TILE_M + m;
            float4 z0 = *(const float4*)(z + (size_t)mg * 8);
            float4 z1 = *(const float4*)(z + (size_t)mg * 8 + 4);
            float zv[8] = {z0.x, z0.y, z0.z, z0.w, z1.x, z1.y, z1.z, z1.w};
#pragma unroll
            for (int c8 = 0; c8 < 8; c8++) {
                int i0 = iq * 32 + c8 * 4;
                float4 acc = *(const float4*)(b1s + i0);
                float4 wt = *(const float4*)(W1s + 8 * Hh + i0);
                acc.x = fmaf(t, wt.x, acc.x); acc.y = fmaf(t, wt.y, acc.y);
                acc.z = fmaf(t, wt.z, acc.z); acc.w = fmaf(t, wt.w, acc.w);
#pragma unroll
                for (int d = 0; d < 8; d++) {
                    float4 w = *(const float4*)(W1s + d * Hh + i0);
                    acc.x = fmaf(zv[d], w.x, acc.x);
                    acc.y = fmaf(zv[d], w.y, acc.y);
                    acc.z = fmaf(zv[d], w.z, acc.z);
                    acc.w = fmaf(zv[d], w.w, acc.w);
                }
                float h0 = ftanh(acc.x), h1 = ftanh(acc.y);
                float h2 = ftanh(acc.z), h3 = ftanh(acc.w);
                float s0 = fmaf(-h0, h0, 1.f), s1v = fmaf(-h1, h1, 1.f);
                float s2 = fmaf(-h2, h2, 1.f), s3 = fmaf(-h3, h3, 1.f);
                float r0, r1, r2, r3, q0, q1, q2, q3;
                uint32_t hh01 = pkhi(h0, h1, r0, r1);
                uint32_t hh23 = pkhi(h2, h3, r2, r3);
                uint32_t sh01 = pkhi(s0, s1v, q0, q1);
                uint32_t sh23 = pkhi(s2, s3, q2, q3);
                int o = m * ASTR + iq * 16 + c8 * 2;
                *(uint2*)&Ahh[o] = make_uint2(hh01, hh23);
                *(uint2*)&Ahl[o] = make_uint2(pk2b(r0, r1), pk2b(r2, r3));
                *(uint2*)&Ash[o] = make_uint2(sh01, sh23);
                *(uint2*)&Asl[o] = make_uint2(pk2b(q0, q1), pk2b(q2, q3));
            }
        }
        __syncthreads();

        // ================= phase B: HMMA with ldmatrix =================
        float cb[8][4], cr[8][4];
#pragma unroll
        for (int nt = 0; nt < 8; nt++)
#pragma unroll
            for (int q = 0; q < 4; q++) { cb[nt][q] = 0.f; cr[nt][q] = 0.f; }

#pragma unroll 1
        for (int kt = 0; kt < 8; kt++) {
            const uint32_t ka = (uint32_t)(kt * 32);
            uint32_t ah[4], al[4], sh[4], sl[4];
            ldsm4(ah, sAhh + ka);
            ldsm4(al, sAhl + ka);
            ldsm4(sh, sAsh + ka);
            ldsm4(sl, sAsl + ka);
#pragma unroll
            for (int p = 0; p < 4; p++) {
                const uint32_t nb = (uint32_t)(p * 16 * BSTR * 4) + ka;
                uint32_t bw[4], bl[4], be[4], bel[4];
                ldsm4(bw, sBwh + nb);
                ldsm4(bl, sBwl + nb);
                ldsm4(be, sBeh + nb);
                ldsm4(bel, sBel + nb);
                mma16816(cb[2 * p],     ah, bw);
                mma16816(cb[2 * p + 1], ah, bw + 2);
                mma16816(cb[2 * p],     al, bw);
                mma16816(cb[2 * p + 1], al, bw + 2);
                mma16816(cb[2 * p],     ah, bl);
                mma16816(cb[2 * p + 1], ah, bl + 2);
                mma16816(cr[2 * p],     sh, be);
                mma16816(cr[2 * p + 1], sh, be + 2);
                mma16816(cr[2 * p],     sl, be);
                mma16816(cr[2 * p + 1], sl, be + 2);
                mma16816(cr[2 * p],     sh, bel);
                mma16816(cr[2 * p + 1], sh, bel + 2);
            }
        }

        // ================= epilogue =================
        float odA[2][8], trA[2];
#pragma unroll
        for (int rh = 0; rh < 2; rh++) {
            float od[8] = {0.f, 0.f, 0.f, 0.f, 0.f, 0.f, 0.f, 0.f};
            float tr = 0.f;
#pragma unroll
            for (int nt = 0; nt < 8; nt++) {
#pragma unroll
                for (int q = 0; q < 2; q++) {
                    int j = wgid * 64 + nt * 8 + lq * 2 + q;
                    float bv = cb[nt][rh * 2 + q] + b2s[j];
                    float h2 = ftanh(bv);
                    float s2v = fmaf(-h2, h2, 1.0f);
                    tr = fmaf(s2v, cr[nt][rh * 2 + q], tr);
                    float4 lo = *(const float4*)&W3s[j * 8];
                    float4 hi = *(const float4*)&W3s[j * 8 + 4];
                    od[0] = fmaf(h2, lo.x, od[0]);
                    od[1] = fmaf(h2, lo.y, od[1]);
                    od[2] = fmaf(h2, lo.z, od[2]);
                    od[3] = fmaf(h2, lo.w, od[3]);
                    od[4] = fmaf(h2, hi.x, od[4]);
                    od[5] = fmaf(h2, hi.y, od[5]);
                    od[6] = fmaf(h2, hi.z, od[6]);
                    od[7] = fmaf(h2, hi.w, od[7]);
                }
            }
#pragma unroll
            for (int off = 1; off <= 2; off <<= 1) {
#pragma unroll
                for (int k = 0; k < 8; k++)
                    od[k] += __shfl_xor_sync(0xffffffffu, od[k], off);
                tr += __shfl_xor_sync(0xffffffffu, tr, off);
            }
#pragma unroll
            for (int k = 0; k < 8; k++) odA[rh][k] = od[k];
            trA[rh] = tr;
        }

        if (wgid == 1 && lq == 0) {
#pragma unroll
            for (int rh = 0; rh < 2; rh++) {
                int mr = wsub * 16 + lr + rh * 8;
                float* pp = part + mr * 9;
#pragma unroll
                for (int k = 0; k < 8; k++) pp[k] = odA[rh][k];
                pp[8] = trA[rh];
            }
        }
        __syncthreads();
        if (wgid == 0 && lq == 0) {
#pragma unroll
            for (int rh = 0; rh < 2; rh++) {
                int mr = wsub * 16 + lr + rh * 8;
                const float* pp = part + mr * 9;
                int mg = tile * TILE_M + mr;
                float* o = out + (size_t)mg * 8;
                float4 v0 = make_float4(odA[rh][0] + pp[0] + b3s[0],
                                        odA[rh][1] + pp[1] + b3s[1],
                                        odA[rh][2] + pp[2] + b3s[2],
                                        odA[rh][3] + pp[3] + b3s[3]);
                float4 v1 = make_float4(odA[rh][4] + pp[4] + b3s[4],
                                        odA[rh][5] + pp[5] + b3s[5],
                                        odA[rh][6] + pp[6] + b3s[6],
                                        odA[rh][7] + pp[7] + b3s[7]);
                *(float4*)o = v0;
                *(float4*)(o + 4) = v1;
                out[(size_t)B * 8 + mg] = -(trA[rh] + pp[8]);
            }
        }
        __syncthreads();
    }
}

extern "C" void kernel_launch(void* const* d_in, const int* in_sizes, int n_in,
                              void* d_out, int out_size) {
    const float* z  = (const float*)d_in[0];
    // d_in[1] = logp_z (unused by reference output)
    const float* t  = (const float*)d_in[2];
    const float* W1 = (const float*)d_in[3];
    const float* b1 = (const float*)d_in[4];
    const float* W2 = (const float*)d_in[5];
    const float* b2 = (const float*)d_in[6];
    const float* W3 = (const float*)d_in[7];
    const float* b3 = (const float*)d_in[8];
    float* out = (float*)d_out;
    int B = in_sizes[0] / Dd;

    cudaFuncSetAttribute(cnf_mma, cudaFuncAttributeMaxDynamicSharedMemorySize,
                         SM_TOTAL);

    prep<<<64, 256>>>(W1, W2, W3);
    cnf_mma<<<NBLK, THREADS, SM_TOTAL>>>(z, t, W1, b1, b2, W3, b3, out, B);
}

// round 10
// speedup vs baseline: 2.0153x; 1.3944x over previous
#include <cuda_runtime.h>
#include <cuda_fp16.h>
#include <cstdint>

// CNF_plain via HMMA fp16 (mma.sync m16n8k16 f16, fp32 accum):
//   bacc = h @ W2,  racc = s1 @ E,  E = W2 .* (W1[:8,:]^T W3^T)
// A (h, s1) single-plane fp16 (|h|,|s1|<=1 -> 2^-12 rel); B split fp16 hi+lo.
// 4 MMA passes: Ah@Bh + Ah@Bl per GEMM.
// R10: m32xn32 warp tiles (TILE_M=64, 2m x 4n warps), tanh.approx, shared
// epilogue W3 loads. Traffic/tile 384KB (was 640KB).

#define Hh 128
#define Dd 8
#define THREADS 256
#define NBLK 148
#define TILE_M 64

#define ASTR 68   // u32 per A row (136 fp16 = 272B)
#define BSTR 68

// SMEM byte offsets
#define SM_HF   0
#define SM_SF   17408
#define SM_WH   34816
#define SM_WL   69632
#define SM_EH   104448
#define SM_EL   139264
#define SM_W1   174080
#define SM_W3   178688
#define SM_B1   182784
#define SM_B2   183296
#define SM_B3   183808
#define SM_PART 183872
#define SM_TOTAL 193088

static __device__ unsigned short g_wh[16384];  // [j][i] = f16_hi(W2[i,j])
static __device__ unsigned short g_wl[16384];
static __device__ unsigned short g_eh[16384];  // [j][i] = f16_hi(E[i,j])
static __device__ unsigned short g_el[16384];

__global__ void prep(const float* __restrict__ W1, const float* __restrict__ W2,
                     const float* __restrict__ W3) {
    int idx = blockIdx.x * blockDim.x + threadIdx.x;
    if (idx >= 16384) return;
    int j = idx >> 7, i = idx & 127;
    float c = 0.f;
#pragma unroll
    for (int d = 0; d < Dd; d++) c = fmaf(W1[d * Hh + i], W3[j * Dd + d], c);
    float w2 = W2[i * Hh + j];
    float e  = w2 * c;
    __half h;
    h = __float2half_rn(w2);
    g_wh[idx] = __half_as_ushort(h);
    g_wl[idx] = __half_as_ushort(__float2half_rn(w2 - __half2float(h)));
    h = __float2half_rn(e);
    g_eh[idx] = __half_as_ushort(h);
    g_el[idx] = __half_as_ushort(__float2half_rn(e - __half2float(h)));
}

__device__ __forceinline__ float tanha(float x) {
    float y; asm("tanh.approx.f32 %0,%1;" : "=f"(y) : "f"(x)); return y;
}

__device__ __forceinline__ uint32_t pkh2(float a, float b) {
    __half2 h = __floats2half2_rn(a, b);
    return *reinterpret_cast<uint32_t*>(&h);
}

__device__ __forceinline__ void mmaf16(float* c, const uint32_t* a,
                                       const uint32_t* b) {
    asm volatile(
        "mma.sync.aligned.m16n8k16.row.col.f32.f16.f16.f32 "
        "{%0,%1,%2,%3}, {%4,%5,%6,%7}, {%8,%9}, {%0,%1,%2,%3};"
        : "+f"(c[0]), "+f"(c[1]), "+f"(c[2]), "+f"(c[3])
        : "r"(a[0]), "r"(a[1]), "r"(a[2]), "r"(a[3]), "r"(b[0]), "r"(b[1]));
}

__device__ __forceinline__ void ldsm4(uint32_t* r, uint32_t a) {
    asm volatile("ldmatrix.sync.aligned.m8n8.x4.shared.b16 {%0,%1,%2,%3},[%4];"
                 : "=r"(r[0]), "=r"(r[1]), "=r"(r[2]), "=r"(r[3]) : "r"(a));
}

__device__ __forceinline__ uint32_t s2u(const void* p) {
    uint32_t a;
    asm("{.reg .u64 t; cvta.to.shared.u64 t, %1; cvt.u32.u64 %0, t;}"
        : "=r"(a) : "l"(p));
    return a;
}

__global__ __launch_bounds__(THREADS, 1)
void cnf_mma(const float* __restrict__ z, const float* __restrict__ tptr,
             const float* __restrict__ W1, const float* __restrict__ b1,
             const float* __restrict__ b2,
             const float* __restrict__ W3, const float* __restrict__ b3,
             float* __restrict__ out, int B) {
    extern __shared__ char smem[];
    uint32_t* Hf = (uint32_t*)(smem + SM_HF);
    uint32_t* Sf = (uint32_t*)(smem + SM_SF);
    float* W1s = (float*)(smem + SM_W1);
    float* W3s = (float*)(smem + SM_W3);
    float* b1s = (float*)(smem + SM_B1);
    float* b2s = (float*)(smem + SM_B2);
    float* b3s = (float*)(smem + SM_B3);
    float* part = (float*)(smem + SM_PART);   // [4 wq][64 m][9]

    const int tid = threadIdx.x;
    const int wid = tid >> 5, lane = tid & 31;
    const int wm = wid >> 2;          // m-half (32 rows)
    const int wq = wid & 3;           // n-quarter (32 cols)
    const int lq = lane & 3, lr = lane >> 2;

    // ---- stage B planes (pad 256B -> 272B rows) ----
    {
        const uint4* s0 = (const uint4*)g_wh;
        const uint4* s1 = (const uint4*)g_wl;
        const uint4* s2 = (const uint4*)g_eh;
        const uint4* s3 = (const uint4*)g_el;
        uint4* d0 = (uint4*)(smem + SM_WH);
        uint4* d1 = (uint4*)(smem + SM_WL);
        uint4* d2 = (uint4*)(smem + SM_EH);
        uint4* d3 = (uint4*)(smem + SM_EL);
        for (int k = tid; k < 2048; k += THREADS) {
            int j = k >> 4, c = k & 15;
            int dsti = j * 17 + c;
            d0[dsti] = s0[k]; d1[dsti] = s1[k];
            d2[dsti] = s2[k]; d3[dsti] = s3[k];
        }
    }
    for (int k = tid; k < 9 * Hh; k += THREADS) W1s[k] = W1[k];
    for (int k = tid; k < Hh * Dd; k += THREADS) W3s[k] = W3[k];
    if (tid < Hh) { b1s[tid] = b1[tid]; b2s[tid] = b2[tid]; }
    if (tid < Dd) b3s[tid] = b3[tid];
    __syncthreads();

    const float t = tptr[0];
    const int m = tid >> 2;           // phase-A sample (0..63)
    const int iq = tid & 3;           // phase-A i-quarter

    // ---- ldmatrix per-thread addresses ----
    const int grp = lane >> 3, l7 = lane & 7;
    // A frag rows: grp0:(m+0,k+0) grp1:(m+8,k+0) grp2:(m+0,k+8) grp3:(m+8,k+8)
    uint32_t sAh[2], sAs[2];
#pragma unroll
    for (int mt = 0; mt < 2; mt++) {
        uint32_t off = (uint32_t)(((wm * 32 + mt * 16 + l7 + (grp & 1) * 8) * ASTR
                                   + (grp >> 1) * 4) * 4);
        sAh[mt] = s2u(Hf) + off;
        sAs[mt] = s2u(Sf) + off;
    }
    // B frag: grp0:(n+0,k+0) grp1:(n+0,k+8) grp2:(n+8,k+0) grp3:(n+8,k+8)
    uint32_t sWh[2], sWl[2], sEh[2], sEl[2];
#pragma unroll
    for (int nh = 0; nh < 2; nh++) {
        uint32_t off = (uint32_t)(((wq * 32 + nh * 16 + l7 + (grp >> 1) * 8) * BSTR
                                   + (grp & 1) * 4) * 4);
        sWh[nh] = s2u(smem + SM_WH) + off;
        sWl[nh] = s2u(smem + SM_WL) + off;
        sEh[nh] = s2u(smem + SM_EH) + off;
        sEl[nh] = s2u(smem + SM_EL) + off;
    }

    const int nTiles = B / TILE_M;
    for (int tile = blockIdx.x; tile < nTiles; tile += gridDim.x) {
        // ================= phase A: layer 1, fp16 planes =================
        {
            const int mg = tile * TILE_M + m;
            float4 z0 = *(const float4*)(z + (size_t)mg * 8);
            float4 z1 = *(const float4*)(z + (size_t)mg * 8 + 4);
            float zv[8] = {z0.x, z0.y, z0.z, z0.w, z1.x, z1.y, z1.z, z1.w};
#pragma unroll
            for (int c8 = 0; c8 < 8; c8++) {
                int i0 = iq * 32 + c8 * 4;
                float4 acc = *(const float4*)(b1s + i0);
                float4 wt = *(const float4*)(W1s + 8 * Hh + i0);
                acc.x = fmaf(t, wt.x, acc.x); acc.y = fmaf(t, wt.y, acc.y);
                acc.z = fmaf(t, wt.z, acc.z); acc.w = fmaf(t, wt.w, acc.w);
#pragma unroll
                for (int d = 0; d < 8; d++) {
                    float4 w = *(const float4*)(W1s + d * Hh + i0);
                    acc.x = fmaf(zv[d], w.x, acc.x);
                    acc.y = fmaf(zv[d], w.y, acc.y);
                    acc.z = fmaf(zv[d], w.z, acc.z);
                    acc.w = fmaf(zv[d], w.w, acc.w);
                }
                float h0 = tanha(acc.x), h1 = tanha(acc.y);
                float h2 = tanha(acc.z), h3 = tanha(acc.w);
                int o = m * ASTR + iq * 16 + c8 * 2;
                *(uint2*)&Hf[o] = make_uint2(pkh2(h0, h1), pkh2(h2, h3));
                *(uint2*)&Sf[o] = make_uint2(
                    pkh2(fmaf(-h0, h0, 1.f), fmaf(-h1, h1, 1.f)),
                    pkh2(fmaf(-h2, h2, 1.f), fmaf(-h3, h3, 1.f)));
            }
        }
        __syncthreads();

        // ================= phase B: HMMA fp16, 4 passes =================
        float cb[2][4][4], cr[2][4][4];
#pragma unroll
        for (int mt = 0; mt < 2; mt++)
#pragma unroll
            for (int nt = 0; nt < 4; nt++)
#pragma unroll
                for (int q = 0; q < 4; q++) { cb[mt][nt][q] = 0.f; cr[mt][nt][q] = 0.f; }

#pragma unroll 1
        for (int kt = 0; kt < 8; kt++) {
            const uint32_t ka = (uint32_t)(kt * 32);
            uint32_t ah[2][4], as_[2][4];
            ldsm4(ah[0], sAh[0] + ka);
            ldsm4(ah[1], sAh[1] + ka);
            ldsm4(as_[0], sAs[0] + ka);
            ldsm4(as_[1], sAs[1] + ka);
#pragma unroll
            for (int nh = 0; nh < 2; nh++) {
                uint32_t bw[4], bl[4], be[4], bel[4];
                ldsm4(bw, sWh[nh] + ka);
                ldsm4(bl, sWl[nh] + ka);
                ldsm4(be, sEh[nh] + ka);
                ldsm4(bel, sEl[nh] + ka);
#pragma unroll
                for (int mt = 0; mt < 2; mt++)
#pragma unroll
                    for (int n8 = 0; n8 < 2; n8++) {
                        int nt = nh * 2 + n8;
                        mmaf16(cb[mt][nt], ah[mt], bw + n8 * 2);
                        mmaf16(cb[mt][nt], ah[mt], bl + n8 * 2);
                        mmaf16(cr[mt][nt], as_[mt], be + n8 * 2);
                        mmaf16(cr[mt][nt], as_[mt], bel + n8 * 2);
                    }
            }
        }

        // ================= epilogue =================
        float od[4][8];
        float tr[4] = {0.f, 0.f, 0.f, 0.f};
#pragma unroll
        for (int r = 0; r < 4; r++)
#pragma unroll
            for (int k = 0; k < 8; k++) od[r][k] = 0.f;

#pragma unroll
        for (int nt = 0; nt < 4; nt++)
#pragma unroll
            for (int q = 0; q < 2; q++) {
                int j = wq * 32 + nt * 8 + lq * 2 + q;
                float bias = b2s[j];
                float4 lo = *(const float4*)&W3s[j * 8];
                float4 hi = *(const float4*)&W3s[j * 8 + 4];
#pragma unroll
                for (int r = 0; r < 4; r++) {
                    int mt = r >> 1, rh = r & 1;
                    float bv = cb[mt][nt][rh * 2 + q] + bias;
                    float h2 = tanha(bv);
                    float s2v = fmaf(-h2, h2, 1.0f);
                    tr[r] = fmaf(s2v, cr[mt][nt][rh * 2 + q], tr[r]);
                    od[r][0] = fmaf(h2, lo.x, od[r][0]);
                    od[r][1] = fmaf(h2, lo.y, od[r][1]);
                    od[r][2] = fmaf(h2, lo.z, od[r][2]);
                    od[r][3] = fmaf(h2, lo.w, od[r][3]);
                    od[r][4] = fmaf(h2, hi.x, od[r][4]);
                    od[r][5] = fmaf(h2, hi.y, od[r][5]);
                    od[r][6] = fmaf(h2, hi.z, od[r][6]);
                    od[r][7] = fmaf(h2, hi.w, od[r][7]);
                }
            }

        // reduce over the 4 lq lanes sharing each row
#pragma unroll
        for (int off = 1; off <= 2; off <<= 1)
#pragma unroll
            for (int r = 0; r < 4; r++) {
#pragma unroll
                for (int k = 0; k < 8; k++)
                    od[r][k] += __shfl_xor_sync(0xffffffffu, od[r][k], off);
                tr[r] += __shfl_xor_sync(0xffffffffu, tr[r], off);
            }

        if (lq == 0) {
#pragma unroll
            for (int r = 0; r < 4; r++) {
                int mt = r >> 1, rh = r & 1;
                int ml = wm * 32 + mt * 16 + rh * 8 + lr;
                float* pp = part + (wq * 64 + ml) * 9;
#pragma unroll
                for (int k = 0; k < 8; k++) pp[k] = od[r][k];
                pp[8] = tr[r];
            }
        }
        __syncthreads();

        // combine 4 n-quarters per sample
        if (tid < TILE_M) {
            const float* p0 = part + (0 * 64 + tid) * 9;
            const float* p1 = part + (1 * 64 + tid) * 9;
            const float* p2 = part + (2 * 64 + tid) * 9;
            const float* p3 = part + (3 * 64 + tid) * 9;
            int mg = tile * TILE_M + tid;
            float* o = out + (size_t)mg * 8;
            float4 v0, v1;
            v0.x = p0[0] + p1[0] + p2[0] + p3[0] + b3s[0];
            v0.y = p0[1] + p1[1] + p2[1] + p3[1] + b3s[1];
            v0.z = p0[2] + p1[2] + p2[2] + p3[2] + b3s[2];
            v0.w = p0[3] + p1[3] + p2[3] + p3[3] + b3s[3];
            v1.x = p0[4] + p1[4] + p2[4] + p3[4] + b3s[4];
            v1.y = p0[5] + p1[5] + p2[5] + p3[5] + b3s[5];
            v1.z = p0[6] + p1[6] + p2[6] + p3[6] + b3s[6];
            v1.w = p0[7] + p1[7] + p2[7] + p3[7] + b3s[7];
            *(float4*)o = v0;
            *(float4*)(o + 4) = v1;
            out[(size_t)B * 8 + mg] = -(p0[8] + p1[8] + p2[8] + p3[8]);
        }
        __syncthreads();
    }
}

extern "C" void kernel_launch(void* const* d_in, const int* in_sizes, int n_in,
                              void* d_out, int out_size) {
    const float* z  = (const float*)d_in[0];
    // d_in[1] = logp_z (unused by reference output)
    const float* t  = (const float*)d_in[2];
    const float* W1 = (const float*)d_in[3];
    const float* b1 = (const float*)d_in[4];
    const float* W2 = (const float*)d_in[5];
    const float* b2 = (const float*)d_in[6];
    const float* W3 = (const float*)d_in[7];
    const float* b3 = (const float*)d_in[8];
    float* out = (float*)d_out;
    int B = in_sizes[0] / Dd;

    cudaFuncSetAttribute(cnf_mma, cudaFuncAttributeMaxDynamicSharedMemorySize,
                         SM_TOTAL);

    prep<<<64, 256>>>(W1, W2, W3);
    cnf_mma<<<NBLK, THREADS, SM_TOTAL>>>(z, t, W1, b1, b2, W3, b3, out, B);
}

// round 11
// speedup vs baseline: 2.0848x; 1.0345x over previous
#include <cuda_runtime.h>
#include <cuda_fp16.h>
#include <cstdint>

// CNF_plain via HMMA fp16 (mma.sync m16n8k16 f16, fp32 accum):
//   bacc = h @ W2,  racc = s1 @ E,  E = W2 .* (W1[:8,:]^T W3^T)
// A (h, s1) single-plane fp16; B split fp16 hi+lo (4 MMA passes).
// R11: 512 threads, TILE_M=128, 16 warps (4m x 4n quarters) for 2x
// occupancy; part buffer aliased over A-plane SMEM (sync-separated).

#define Hh 128
#define Dd 8
#define THREADS 512
#define NBLK 148
#define TILE_M 128

#define ASTR 68   // u32 per A row (136 fp16 = 272B)
#define BSTR 68

// SMEM byte offsets
#define SM_HF   0
#define SM_SF   34816
#define SM_WH   69632
#define SM_WL   104448
#define SM_EH   139264
#define SM_EL   174080
#define SM_W1   208896
#define SM_W3   213504
#define SM_B1   217600
#define SM_B2   218112
#define SM_B3   218624
#define SM_PART 0          // aliased over Hf (sync-separated)
#define SM_TOTAL 218688

static __device__ unsigned short g_wh[16384];  // [j][i] = f16_hi(W2[i,j])
static __device__ unsigned short g_wl[16384];
static __device__ unsigned short g_eh[16384];  // [j][i] = f16_hi(E[i,j])
static __device__ unsigned short g_el[16384];

__global__ void prep(const float* __restrict__ W1, const float* __restrict__ W2,
                     const float* __restrict__ W3) {
    int idx = blockIdx.x * blockDim.x + threadIdx.x;
    if (idx >= 16384) return;
    int j = idx >> 7, i = idx & 127;
    float c = 0.f;
#pragma unroll
    for (int d = 0; d < Dd; d++) c = fmaf(W1[d * Hh + i], W3[j * Dd + d], c);
    float w2 = W2[i * Hh + j];
    float e  = w2 * c;
    __half h;
    h = __float2half_rn(w2);
    g_wh[idx] = __half_as_ushort(h);
    g_wl[idx] = __half_as_ushort(__float2half_rn(w2 - __half2float(h)));
    h = __float2half_rn(e);
    g_eh[idx] = __half_as_ushort(h);
    g_el[idx] = __half_as_ushort(__float2half_rn(e - __half2float(h)));
}

__device__ __forceinline__ float tanha(float x) {
    float y; asm("tanh.approx.f32 %0,%1;" : "=f"(y) : "f"(x)); return y;
}

__device__ __forceinline__ uint32_t pkh2(float a, float b) {
    __half2 h = __floats2half2_rn(a, b);
    return *reinterpret_cast<uint32_t*>(&h);
}

__device__ __forceinline__ void mmaf16(float* c, const uint32_t* a,
                                       const uint32_t* b) {
    asm volatile(
        "mma.sync.aligned.m16n8k16.row.col.f32.f16.f16.f32 "
        "{%0,%1,%2,%3}, {%4,%5,%6,%7}, {%8,%9}, {%0,%1,%2,%3};"
        : "+f"(c[0]), "+f"(c[1]), "+f"(c[2]), "+f"(c[3])
        : "r"(a[0]), "r"(a[1]), "r"(a[2]), "r"(a[3]), "r"(b[0]), "r"(b[1]));
}

__device__ __forceinline__ void ldsm4(uint32_t* r, uint32_t a) {
    asm volatile("ldmatrix.sync.aligned.m8n8.x4.shared.b16 {%0,%1,%2,%3},[%4];"
                 : "=r"(r[0]), "=r"(r[1]), "=r"(r[2]), "=r"(r[3]) : "r"(a));
}

__device__ __forceinline__ uint32_t s2u(const void* p) {
    uint32_t a;
    asm("{.reg .u64 t; cvta.to.shared.u64 t, %1; cvt.u32.u64 %0, t;}"
        : "=r"(a) : "l"(p));
    return a;
}

__global__ __launch_bounds__(THREADS, 1)
void cnf_mma(const float* __restrict__ z, const float* __restrict__ tptr,
             const float* __restrict__ W1, const float* __restrict__ b1,
             const float* __restrict__ b2,
             const float* __restrict__ W3, const float* __restrict__ b3,
             float* __restrict__ out, int B) {
    extern __shared__ char smem[];
    uint32_t* Hf = (uint32_t*)(smem + SM_HF);
    uint32_t* Sf = (uint32_t*)(smem + SM_SF);
    float* W1s = (float*)(smem + SM_W1);
    float* W3s = (float*)(smem + SM_W3);
    float* b1s = (float*)(smem + SM_B1);
    float* b2s = (float*)(smem + SM_B2);
    float* b3s = (float*)(smem + SM_B3);
    float* part = (float*)(smem + SM_PART);   // [4 wq][128 m][9], aliases Hf

    const int tid = threadIdx.x;
    const int wid = tid >> 5, lane = tid & 31;
    const int wm = wid >> 2;          // m-quarter (32 rows)
    const int wq = wid & 3;           // n-quarter (32 cols)
    const int lq = lane & 3, lr = lane >> 2;

    // ---- stage B planes (pad 256B -> 272B rows) ----
    {
        const uint4* s0 = (const uint4*)g_wh;
        const uint4* s1 = (const uint4*)g_wl;
        const uint4* s2 = (const uint4*)g_eh;
        const uint4* s3 = (const uint4*)g_el;
        uint4* d0 = (uint4*)(smem + SM_WH);
        uint4* d1 = (uint4*)(smem + SM_WL);
        uint4* d2 = (uint4*)(smem + SM_EH);
        uint4* d3 = (uint4*)(smem + SM_EL);
        for (int k = tid; k < 2048; k += THREADS) {
            int j = k >> 4, c = k & 15;
            int dsti = j * 17 + c;
            d0[dsti] = s0[k]; d1[dsti] = s1[k];
            d2[dsti] = s2[k]; d3[dsti] = s3[k];
        }
    }
    for (int k = tid; k < 9 * Hh; k += THREADS) W1s[k] = W1[k];
    for (int k = tid; k < Hh * Dd; k += THREADS) W3s[k] = W3[k];
    if (tid < Hh) { b1s[tid] = b1[tid]; b2s[tid] = b2[tid]; }
    if (tid < Dd) b3s[tid] = b3[tid];
    __syncthreads();

    const float t = tptr[0];
    const int m = tid >> 2;           // phase-A sample (0..127)
    const int iq = tid & 3;           // phase-A i-quarter

    // ---- ldmatrix per-thread addresses ----
    const int grp = lane >> 3, l7 = lane & 7;
    uint32_t sAh[2], sAs[2];
#pragma unroll
    for (int mt = 0; mt < 2; mt++) {
        uint32_t off = (uint32_t)(((wm * 32 + mt * 16 + l7 + (grp & 1) * 8) * ASTR
                                   + (grp >> 1) * 4) * 4);
        sAh[mt] = s2u(smem + SM_HF) + off;
        sAs[mt] = s2u(smem + SM_SF) + off;
    }
    uint32_t sWh[2], sWl[2], sEh[2], sEl[2];
#pragma unroll
    for (int nh = 0; nh < 2; nh++) {
        uint32_t off = (uint32_t)(((wq * 32 + nh * 16 + l7 + (grp >> 1) * 8) * BSTR
                                   + (grp & 1) * 4) * 4);
        sWh[nh] = s2u(smem + SM_WH) + off;
        sWl[nh] = s2u(smem + SM_WL) + off;
        sEh[nh] = s2u(smem + SM_EH) + off;
        sEl[nh] = s2u(smem + SM_EL) + off;
    }

    const int nTiles = B / TILE_M;
    for (int tile = blockIdx.x; tile < nTiles; tile += gridDim.x) {
        // ================= phase A: layer 1, fp16 planes =================
        {
            const int mg = tile * TILE_M + m;
            float4 z0 = *(const float4*)(z + (size_t)mg * 8);
            float4 z1 = *(const float4*)(z + (size_t)mg * 8 + 4);
            float zv[8] = {z0.x, z0.y, z0.z, z0.w, z1.x, z1.y, z1.z, z1.w};
#pragma unroll
            for (int c8 = 0; c8 < 8; c8++) {
                int i0 = iq * 32 + c8 * 4;
                float4 acc = *(const float4*)(b1s + i0);
                float4 wt = *(const float4*)(W1s + 8 * Hh + i0);
                acc.x = fmaf(t, wt.x, acc.x); acc.y = fmaf(t, wt.y, acc.y);
                acc.z = fmaf(t, wt.z, acc.z); acc.w = fmaf(t, wt.w, acc.w);
#pragma unroll
                for (int d = 0; d < 8; d++) {
                    float4 w = *(const float4*)(W1s + d * Hh + i0);
                    acc.x = fmaf(zv[d], w.x, acc.x);
                    acc.y = fmaf(zv[d], w.y, acc.y);
                    acc.z = fmaf(zv[d], w.z, acc.z);
                    acc.w = fmaf(zv[d], w.w, acc.w);
                }
                float h0 = tanha(acc.x), h1 = tanha(acc.y);
                float h2 = tanha(acc.z), h3 = tanha(acc.w);
                int o = m * ASTR + iq * 16 + c8 * 2;
                *(uint2*)&Hf[o] = make_uint2(pkh2(h0, h1), pkh2(h2, h3));
                *(uint2*)&Sf[o] = make_uint2(
                    pkh2(fmaf(-h0, h0, 1.f), fmaf(-h1, h1, 1.f)),
                    pkh2(fmaf(-h2, h2, 1.f), fmaf(-h3, h3, 1.f)));
            }
        }
        __syncthreads();

        // ================= phase B: HMMA fp16, 4 passes =================
        float cb[2][4][4], cr[2][4][4];
#pragma unroll
        for (int mt = 0; mt < 2; mt++)
#pragma unroll
            for (int nt = 0; nt < 4; nt++)
#pragma unroll
                for (int q = 0; q < 4; q++) { cb[mt][nt][q] = 0.f; cr[mt][nt][q] = 0.f; }

#pragma unroll 1
        for (int kt = 0; kt < 8; kt++) {
            const uint32_t ka = (uint32_t)(kt * 32);
            uint32_t ah[2][4], as_[2][4];
            ldsm4(ah[0], sAh[0] + ka);
            ldsm4(ah[1], sAh[1] + ka);
            ldsm4(as_[0], sAs[0] + ka);
            ldsm4(as_[1], sAs[1] + ka);
#pragma unroll
            for (int nh = 0; nh < 2; nh++) {
                uint32_t bw[4], bl[4], be[4], bel[4];
                ldsm4(bw, sWh[nh] + ka);
                ldsm4(bl, sWl[nh] + ka);
                ldsm4(be, sEh[nh] + ka);
                ldsm4(bel, sEl[nh] + ka);
#pragma unroll
                for (int mt = 0; mt < 2; mt++)
#pragma unroll
                    for (int n8 = 0; n8 < 2; n8++) {
                        int nt = nh * 2 + n8;
                        mmaf16(cb[mt][nt], ah[mt], bw + n8 * 2);
                        mmaf16(cb[mt][nt], ah[mt], bl + n8 * 2);
                        mmaf16(cr[mt][nt], as_[mt], be + n8 * 2);
                        mmaf16(cr[mt][nt], as_[mt], bel + n8 * 2);
                    }
            }
        }
        // all ldmatrix reads of Hf/Sf done before part (aliased) is written
        __syncthreads();

        // ================= epilogue =================
        float od[4][8];
        float tr[4] = {0.f, 0.f, 0.f, 0.f};
#pragma unroll
        for (int r = 0; r < 4; r++)
#pragma unroll
            for (int k = 0; k < 8; k++) od[r][k] = 0.f;

#pragma unroll
        for (int nt = 0; nt < 4; nt++)
#pragma unroll
            for (int q = 0; q < 2; q++) {
                int j = wq * 32 + nt * 8 + lq * 2 + q;
                float bias = b2s[j];
                float4 lo = *(const float4*)&W3s[j * 8];
                float4 hi = *(const float4*)&W3s[j * 8 + 4];
#pragma unroll
                for (int r = 0; r < 4; r++) {
                    int mt = r >> 1, rh = r & 1;
                    float bv = cb[mt][nt][rh * 2 + q] + bias;
                    float h2 = tanha(bv);
                    float s2v = fmaf(-h2, h2, 1.0f);
                    tr[r] = fmaf(s2v, cr[mt][nt][rh * 2 + q], tr[r]);
                    od[r][0] = fmaf(h2, lo.x, od[r][0]);
                    od[r][1] = fmaf(h2, lo.y, od[r][1]);
                    od[r][2] = fmaf(h2, lo.z, od[r][2]);
                    od[r][3] = fmaf(h2, lo.w, od[r][3]);
                    od[r][4] = fmaf(h2, hi.x, od[r][4]);
                    od[r][5] = fmaf(h2, hi.y, od[r][5]);
                    od[r][6] = fmaf(h2, hi.z, od[r][6]);
                    od[r][7] = fmaf(h2, hi.w, od[r][7]);
                }
            }

        // reduce over the 4 lq lanes sharing each row
#pragma unroll
        for (int off = 1; off <= 2; off <<= 1)
#pragma unroll
            for (int r = 0; r < 4; r++) {
#pragma unroll
                for (int k = 0; k < 8; k++)
                    od[r][k] += __shfl_xor_sync(0xffffffffu, od[r][k], off);
                tr[r] += __shfl_xor_sync(0xffffffffu, tr[r], off);
            }

        if (lq == 0) {
#pragma unroll
            for (int r = 0; r < 4; r++) {
                int mt = r >> 1, rh = r & 1;
                int ml = wm * 32 + mt * 16 + rh * 8 + lr;
                float* pp = part + (wq * TILE_M + ml) * 9;
#pragma unroll
                for (int k = 0; k < 8; k++) pp[k] = od[r][k];
                pp[8] = tr[r];
            }
        }
        __syncthreads();

        // combine 4 n-quarters per sample
        if (tid < TILE_M) {
            const float* p0 = part + (0 * TILE_M + tid) * 9;
            const float* p1 = part + (1 * TILE_M + tid) * 9;
            const float* p2 = part + (2 * TILE_M + tid) * 9;
            const float* p3 = part + (3 * TILE_M + tid) * 9;
            int mg = tile * TILE_M + tid;
            float* o = out + (size_t)mg * 8;
            float4 v0, v1;
            v0.x = p0[0] + p1[0] + p2[0] + p3[0] + b3s[0];
            v0.y = p0[1] + p1[1] + p2[1] + p3[1] + b3s[1];
            v0.z = p0[2] + p1[2] + p2[2] + p3[2] + b3s[2];
            v0.w = p0[3] + p1[3] + p2[3] + p3[3] + b3s[3];
            v1.x = p0[4] + p1[4] + p2[4] + p3[4] + b3s[4];
            v1.y = p0[5] + p1[5] + p2[5] + p3[5] + b3s[5];
            v1.z = p0[6] + p1[6] + p2[6] + p3[6] + b3s[6];
            v1.w = p0[7] + p1[7] + p2[7] + p3[7] + b3s[7];
            *(float4*)o = v0;
            *(float4*)(o + 4) = v1;
            out[(size_t)B * 8 + mg] = -(p0[8] + p1[8] + p2[8] + p3[8]);
        }
        __syncthreads();   // part read done before next tile's Hf writes
    }
}

extern "C" void kernel_launch(void* const* d_in, const int* in_sizes, int n_in,
                              void* d_out, int out_size) {
    const float* z  = (const float*)d_in[0];
    // d_in[1] = logp_z (unused by reference output)
    const float* t  = (const float*)d_in[2];
    const float* W1 = (const float*)d_in[3];
    const float* b1 = (const float*)d_in[4];
    const float* W2 = (const float*)d_in[5];
    const float* b2 = (const float*)d_in[6];
    const float* W3 = (const float*)d_in[7];
    const float* b3 = (const float*)d_in[8];
    float* out = (float*)d_out;
    int B = in_sizes[0] / Dd;

    cudaFuncSetAttribute(cnf_mma, cudaFuncAttributeMaxDynamicSharedMemorySize,
                         SM_TOTAL);

    prep<<<64, 256>>>(W1, W2, W3);
    cnf_mma<<<NBLK, THREADS, SM_TOTAL>>>(z, t, W1, b1, b2, W3, b3, out, B);
}